// round 16
// baseline (speedup 1.0000x reference)
#include <cuda_runtime.h>
#include <math.h>

// ---------------- problem constants ----------------
#define HIDC 128
#define NMAX 50000
#define EMAX 600000
#define SCAN_BLK 512

// ---------------- device scratch ----------------
__device__ __align__(128) float g_h    [NMAX * HIDC];
__device__ __align__(128) float g_xh   [NMAX * HIDC];
__device__ __align__(128) float g_acc  [NMAX * HIDC];
__device__ __align__(128) float g_asrc [NMAX * 4];
__device__ __align__(128) float g_adst [NMAX * 4];
__device__ __align__(128) float g_M    [3 * 64];
__device__ __align__(128) float g_c    [3 * 4];
__device__ int   g_degi  [NMAX];
__device__ int   g_fill  [NMAX];
__device__ int   g_rowptr[NMAX];
__device__ int   g_bsum  [256];
__device__ __align__(128) int   g_csrc[EMAX];
__device__ __align__(128) float g_ae  [3][EMAX * 4];   // folded edge logits, CSR order
__device__ __align__(128) float g_w   [EMAX * 4];      // fallback scratch (deg>64 only)
__device__ double g_bnsum[HIDC];
__device__ double g_bnsq [HIDC];
__device__ __align__(128) float g_bnscale[HIDC];
__device__ __align__(128) float g_bnshift[HIDC];
__device__ unsigned int g_ctr = 0;

// ---------------- helpers ----------------
__device__ __forceinline__ float lrelu(float a) { return a > 0.f ? a : 0.2f * a; }

__device__ __forceinline__ unsigned long long pack2(float a) {
    unsigned long long r;
    asm("mov.b64 %0, {%1, %1};" : "=l"(r) : "r"(__float_as_uint(a)));
    return r;
}
__device__ __forceinline__ float2 unpack2(unsigned long long v) {
    unsigned int lo, hi;
    asm("mov.b64 {%0, %1}, %2;" : "=r"(lo), "=r"(hi) : "l"(v));
    return make_float2(__uint_as_float(lo), __uint_as_float(hi));
}
#define FMA2(acc, a2, b2) \
    asm("fma.rn.f32x2 %0, %1, %2, %0;" : "+l"(acc) : "l"(a2), "l"(b2))

__device__ __forceinline__ float sel4(float4 v, int h) {
    float ab = (h & 1) ? v.y : v.x;
    float cd = (h & 1) ? v.w : v.z;
    return (h & 2) ? cd : ab;
}
__device__ __forceinline__ float4 fmax4(float4 a, float4 b) {
    return make_float4(fmaxf(a.x, b.x), fmaxf(a.y, b.y), fmaxf(a.z, b.z), fmaxf(a.w, b.w));
}

// ---------------- prep: zeros + folded constants (consts fused as 12 extra blocks) ----------------
// M[l][k][h] = sum_j W_bond[k][j]*Ve[j][h], Ve[j][h] = sum_d W_edge[l][j][h*32+d]*att_edge[l][h*32+d]
__global__ void prep_kernel(int nz, int N,
                            const float* __restrict__ W_edge,
                            const float* __restrict__ att_edge,
                            const float* __restrict__ W_bond,
                            const float* __restrict__ b_bond) {
    if ((int)blockIdx.x < nz) {
        int i = blockIdx.x * 256 + threadIdx.x;
        if (i < N) { g_degi[i] = 0; g_fill[i] = 0; }
        if (i < 128) { g_bnsum[i] = 0.0; g_bnsq[i] = 0.0; }
        return;
    }
    __shared__ float Ve[128];
    const int cb = blockIdx.x - nz;     // 0..11
    const int l = cb >> 2;              // layer
    const int h = cb & 3;               // head
    const int t = threadIdx.x;
    if (t < 128) {
        const float* We = W_edge + l * 128 * 128 + t * 128 + h * 32;
        const float* ae = att_edge + l * 128 + h * 32;
        float v = 0.f;
#pragma unroll
        for (int d = 0; d < 32; d++) v += We[d] * ae[d];
        Ve[t] = v;
    }
    __syncthreads();
    if (t < 16) {
        float m = 0.f;
        const float* wb = W_bond + t * 128;
#pragma unroll 4
        for (int k = 0; k < 128; k++) m += wb[k] * Ve[k];
        g_M[l * 64 + t * 4 + h] = m;
    } else if (t == 16) {
        float cc = 0.f;
        for (int k = 0; k < 128; k++) cc += b_bond[k] * Ve[k];
        g_c[l * 4 + h] = cc;
    }
}

// ---------------- degree histogram only ----------------
__global__ void edge_prep_kernel(const int* __restrict__ ei, int E) {
    int e = blockIdx.x * blockDim.x + threadIdx.x;
    if (e < E) atomicAdd(&g_degi[ei[E + e]], 1);
}

// ---------------- scan: per-block sums ----------------
__global__ void scan_sum_kernel(int N) {
    __shared__ int sh[16];
    int b = blockIdx.x, t = threadIdx.x;
    int i = b * SCAN_BLK + t;
    int v = (i < N) ? g_degi[i] : 0;
#pragma unroll
    for (int o = 16; o; o >>= 1) v += __shfl_xor_sync(0xffffffffu, v, o);
    if ((t & 31) == 0) sh[t >> 5] = v;
    __syncthreads();
    if (t < 16) {
        int s = sh[t];
#pragma unroll
        for (int o = 8; o; o >>= 1) s += __shfl_xor_sync(0xffffu, s, o);
        if (t == 0) g_bsum[b] = s;
    }
}
// ---------------- scan: final (block base computed in-kernel from raw bsum) ----------------
__global__ void scan_final_kernel(int N, int nb) {
    __shared__ int wsum[16];
    __shared__ int sbase[4];
    int b = blockIdx.x, t = threadIdx.x;
    int lane = t & 31, w = t >> 5;

    // base = sum of g_bsum[j] for j < b  (nb <= 128, threads 0..127 participate)
    if (t < 128) {
        int pv = (t < nb && t < b) ? g_bsum[t] : 0;
#pragma unroll
        for (int o = 16; o; o >>= 1) pv += __shfl_xor_sync(0xffffffffu, pv, o);
        if (lane == 0) sbase[w] = pv;
    }

    int i = b * SCAN_BLK + t;
    int v = (i < N) ? g_degi[i] : 0;
    int x = v;
#pragma unroll
    for (int o = 1; o < 32; o <<= 1) {
        int y = __shfl_up_sync(0xffffffffu, x, o);
        if (lane >= o) x += y;
    }
    if (lane == 31) wsum[w] = x;
    __syncthreads();
    if (t == 0) {
        int acc = 0;
        for (int q = 0; q < 16; q++) { int s = wsum[q]; wsum[q] = acc; acc += s; }
    }
    __syncthreads();
    int base = sbase[0] + sbase[1] + sbase[2] + sbase[3];
    if (i < N) g_rowptr[i] = x - v + wsum[w] + base;
}

// ---------------- counting-sort scatter: csr_src + folded edge logits per layer ----------------
__global__ void scatter_kernel(const int* __restrict__ ei,
                               const float* __restrict__ edge_attr, int E) {
    __shared__ float Ms[192];
    __shared__ float Cs[12];
    int t = threadIdx.x;
    if (t < 192) Ms[t] = g_M[t];
    if (t < 12)  Cs[t] = g_c[t];
    __syncthreads();
    int e = blockIdx.x * blockDim.x + t;
    if (e >= E) return;
    int s = ei[e], d = ei[E + e];
    int pos = g_rowptr[d] + atomicAdd(&g_fill[d], 1);
    g_csrc[pos] = s;
    float ev[16];
    const float4* ep = ((const float4*)edge_attr) + e * 4;
#pragma unroll
    for (int q = 0; q < 4; q++) {
        float4 v = ep[q];
        ev[4 * q] = v.x; ev[4 * q + 1] = v.y; ev[4 * q + 2] = v.z; ev[4 * q + 3] = v.w;
    }
#pragma unroll
    for (int l = 0; l < 3; l++) {
        float a0 = Cs[l * 4 + 0], a1 = Cs[l * 4 + 1], a2 = Cs[l * 4 + 2], a3 = Cs[l * 4 + 3];
#pragma unroll
        for (int k = 0; k < 16; k++) {
            float v = ev[k];
            a0 += v * Ms[l * 64 + k * 4 + 0]; a1 += v * Ms[l * 64 + k * 4 + 1];
            a2 += v * Ms[l * 64 + k * 4 + 2]; a3 += v * Ms[l * 64 + k * 4 + 3];
        }
        ((float4*)g_ae[l])[pos] = make_float4(a0, a1, a2, a3);
    }
}

// ---------------- GEMM: C[M,128] = A'[M,K] @ B[K,128] (+ bias) ----------------
// FUSEBN: A' = relu(A*bnscale+bnshift) + hres; WRITEH: write A' back to hres.
template <int K, bool FUSEBN, bool ATT, bool WRITEH>
__global__ __launch_bounds__(256) void gemm_kernel(const float* __restrict__ A,
                                                   const float* __restrict__ B,
                                                   const float* __restrict__ bias,
                                                   float* __restrict__ C,
                                                   float* __restrict__ hres,
                                                   const float* __restrict__ att_src,
                                                   const float* __restrict__ att_dst,
                                                   int l, int M) {
    constexpr int AST = K + 4;
    extern __shared__ float sm[];
    float* Bs = sm;               // K*128
    float* As = sm + K * 128;     // 64*AST
    const int t = threadIdx.x;
    const int row0 = blockIdx.x * 64;

    for (int idx = t; idx < K * 32; idx += 256)
        ((float4*)Bs)[idx] = ((const float4*)B)[idx];

    constexpr int KQ = K / 4;
    for (int idx = t; idx < 64 * KQ; idx += 256) {
        int r = idx / KQ, q = idx - r * KQ;
        int grow = row0 + r;
        float4 o = make_float4(0.f, 0.f, 0.f, 0.f);
        if (grow < M) {
            float4 v = ((const float4*)(A + (size_t)grow * K))[q];
            if (FUSEBN) {
                float4 hv = ((const float4*)(hres + (size_t)grow * K))[q];
                float4 sc = __ldg(((const float4*)g_bnscale) + q);
                float4 sh = __ldg(((const float4*)g_bnshift) + q);
                o.x = fmaxf(fmaf(v.x, sc.x, sh.x), 0.f) + hv.x;
                o.y = fmaxf(fmaf(v.y, sc.y, sh.y), 0.f) + hv.y;
                o.z = fmaxf(fmaf(v.z, sc.z, sh.z), 0.f) + hv.z;
                o.w = fmaxf(fmaf(v.w, sc.w, sh.w), 0.f) + hv.w;
                if (WRITEH) ((float4*)(hres + (size_t)grow * K))[q] = o;
            } else {
                o = v;
            }
        }
        *(float4*)(As + r * AST + 4 * q) = o;
    }
    __syncthreads();

    const int j = t & 15;   // cols 8j..8j+7
    const int i = t >> 4;   // rows 4i..4i+3
    unsigned long long acc2[4][4] = {};

    const float* aBase = As + (4 * i) * AST;
    const ulonglong2* BsP = (const ulonglong2*)Bs;
#pragma unroll 2
    for (int k4 = 0; k4 < K / 4; k4++) {
        float4 av[4];
#pragma unroll
        for (int r = 0; r < 4; r++)
            av[r] = *(const float4*)(aBase + r * AST + 4 * k4);
#pragma unroll
        for (int kk = 0; kk < 4; kk++) {
            int k = 4 * k4 + kk;
            ulonglong2 b01 = BsP[k * 32 + 2 * j];
            ulonglong2 b23 = BsP[k * 32 + 2 * j + 1];
#pragma unroll
            for (int r = 0; r < 4; r++) {
                unsigned long long ap = pack2(((const float*)&av[r])[kk]);
                FMA2(acc2[r][0], ap, b01.x);
                FMA2(acc2[r][1], ap, b01.y);
                FMA2(acc2[r][2], ap, b23.x);
                FMA2(acc2[r][3], ap, b23.y);
            }
        }
    }

    float4 bb0 = make_float4(0.f, 0.f, 0.f, 0.f), bb1 = bb0;
    if (bias) { bb0 = ((const float4*)bias)[2 * j]; bb1 = ((const float4*)bias)[2 * j + 1]; }

    float4 s0, s1, d0, d1;
    if (ATT) {
        s0 = __ldg(((const float4*)(att_src + l * 128)) + 2 * j);
        s1 = __ldg(((const float4*)(att_src + l * 128)) + 2 * j + 1);
        d0 = __ldg(((const float4*)(att_dst + l * 128)) + 2 * j);
        d1 = __ldg(((const float4*)(att_dst + l * 128)) + 2 * j + 1);
    }
    float ps[4], pd[4];

#pragma unroll
    for (int r = 0; r < 4; r++) {
        int grow = row0 + 4 * i + r;
        float2 p0 = unpack2(acc2[r][0]);
        float2 p1 = unpack2(acc2[r][1]);
        float2 p2 = unpack2(acc2[r][2]);
        float2 p3 = unpack2(acc2[r][3]);
        float4 o0 = make_float4(p0.x + bb0.x, p0.y + bb0.y, p1.x + bb0.z, p1.y + bb0.w);
        float4 o1 = make_float4(p2.x + bb1.x, p2.y + bb1.y, p3.x + bb1.z, p3.y + bb1.w);
        if (grow < M) {
            float4* cp = (float4*)(C + (size_t)grow * 128);
            cp[2 * j]     = o0;
            cp[2 * j + 1] = o1;
        }
        if (ATT) {
            ps[r] = o0.x * s0.x + o0.y * s0.y + o0.z * s0.z + o0.w * s0.w
                  + o1.x * s1.x + o1.y * s1.y + o1.z * s1.z + o1.w * s1.w;
            pd[r] = o0.x * d0.x + o0.y * d0.y + o0.z * d0.z + o0.w * d0.w
                  + o1.x * d1.x + o1.y * d1.y + o1.z * d1.z + o1.w * d1.w;
        }
    }

    if (ATT) {
#pragma unroll
        for (int r = 0; r < 4; r++) {
#pragma unroll
            for (int o = 1; o < 4; o <<= 1) {
                ps[r] += __shfl_xor_sync(0xffffffffu, ps[r], o);
                pd[r] += __shfl_xor_sync(0xffffffffu, pd[r], o);
            }
        }
        if ((j & 3) == 0) {
            const int hh = j >> 2;
#pragma unroll
            for (int r = 0; r < 4; r++) {
                int grow = row0 + 4 * i + r;
                if (grow >= M) continue;
                g_asrc[grow * 4 + hh] = ps[r];
                g_adst[grow * 4 + hh] = pd[r];
            }
        }
    }
}

// ---------------- fused GAT: softmax + aggregate + BN stats (fused bnstats tail) ----------------
__global__ __launch_bounds__(256) void gat_kernel(const float* __restrict__ bias_conv,
                                                  const float* __restrict__ gamma,
                                                  const float* __restrict__ beta,
                                                  int l, int N) {
    __shared__ float4 swq[8][64];    // per-warp exp'd weights
    __shared__ int    sid[8][64];    // per-warp neighbor indices
    __shared__ float  sred[8][128];

    const int lane = threadIdx.x & 31;
    const int wl = threadIdx.x >> 5;
    const int warpsTotal = (gridDim.x * blockDim.x) >> 5;
    const int h = lane >> 3;
    const float4* aeB = (const float4*)g_ae[l];
    const float4 bq = __ldg(((const float4*)(bias_conv + l * 128)) + lane);
    const float NEG = -3.0e38f;

    float bs1[4] = {0.f, 0.f, 0.f, 0.f};
    float bs2[4] = {0.f, 0.f, 0.f, 0.f};

    int d = (blockIdx.x * blockDim.x + threadIdx.x) >> 5;
    int start = 0, deg = 0;
    float4 ad, asd;
    if (d < N) {
        start = __ldg(g_rowptr + d);
        deg   = __ldg(g_degi + d);
        ad    = __ldg(((const float4*)g_adst) + d);
        asd   = __ldg(((const float4*)g_asrc) + d);
    }

    while (d < N) {
        const int dn = d + warpsTotal;
        int nstart = 0, ndeg = 0;
        float4 nad, nasd;
        if (dn < N) {
            nstart = __ldg(g_rowptr + dn);
            ndeg   = __ldg(g_degi + dn);
            nad    = __ldg(((const float4*)g_adst) + dn);
            nasd   = __ldg(((const float4*)g_asrc) + dn);
        }

        float4 aes = make_float4(0.f, 0.f, 0.f, 0.f);
        float4 den = make_float4(0.f, 0.f, 0.f, 0.f);

        if (deg <= 64) {
            const bool v0 = lane < deg, v1 = lane + 32 < deg;
            if (v0) {
                int s = __ldg(g_csrc + start + lane);
                sid[wl][lane] = s;
                float4 as = __ldg(((const float4*)g_asrc) + s);
                float4 ae = __ldg(aeB + start + lane);
                aes.x += ae.x; aes.y += ae.y; aes.z += ae.z; aes.w += ae.w;
                float4 e;
                e.x = __expf(lrelu(as.x + ad.x + ae.x));
                e.y = __expf(lrelu(as.y + ad.y + ae.y));
                e.z = __expf(lrelu(as.z + ad.z + ae.z));
                e.w = __expf(lrelu(as.w + ad.w + ae.w));
                swq[wl][lane] = e;
                den.x += e.x; den.y += e.y; den.z += e.z; den.w += e.w;
            }
            if (v1) {
                int s = __ldg(g_csrc + start + lane + 32);
                sid[wl][lane + 32] = s;
                float4 as = __ldg(((const float4*)g_asrc) + s);
                float4 ae = __ldg(aeB + start + lane + 32);
                aes.x += ae.x; aes.y += ae.y; aes.z += ae.z; aes.w += ae.w;
                float4 e;
                e.x = __expf(lrelu(as.x + ad.x + ae.x));
                e.y = __expf(lrelu(as.y + ad.y + ae.y));
                e.z = __expf(lrelu(as.z + ad.z + ae.z));
                e.w = __expf(lrelu(as.w + ad.w + ae.w));
                swq[wl][lane + 32] = e;
                den.x += e.x; den.y += e.y; den.z += e.z; den.w += e.w;
            }
#pragma unroll
            for (int o = 16; o; o >>= 1) {
                aes.x += __shfl_xor_sync(0xffffffffu, aes.x, o);
                aes.y += __shfl_xor_sync(0xffffffffu, aes.y, o);
                aes.z += __shfl_xor_sync(0xffffffffu, aes.z, o);
                aes.w += __shfl_xor_sync(0xffffffffu, aes.w, o);
                den.x += __shfl_xor_sync(0xffffffffu, den.x, o);
                den.y += __shfl_xor_sync(0xffffffffu, den.y, o);
                den.z += __shfl_xor_sync(0xffffffffu, den.z, o);
                den.w += __shfl_xor_sync(0xffffffffu, den.w, o);
            }
            float asfh;
            if (deg > 0) {
                float rdeg = 1.f / (float)deg;
                asfh = lrelu(sel4(asd, h) + sel4(ad, h) + sel4(aes, h) * rdeg);
            } else {
                asfh = lrelu(sel4(asd, h) + sel4(ad, h));
            }
            float wsh = __expf(asfh);
            float rdh = 1.f / (sel4(den, h) + wsh + 1e-16f);
            __syncwarp();

            float4 acc = __ldg(((const float4*)g_xh) + (size_t)d * 32 + lane);
            acc.x *= wsh; acc.y *= wsh; acc.z *= wsh; acc.w *= wsh;
            float4 accB = make_float4(0.f, 0.f, 0.f, 0.f);

            int jj = 0;
            for (; jj + 8 <= deg; jj += 8) {
                int   si[8];
                float wv[8];
#pragma unroll
                for (int q = 0; q < 8; q++) {
                    si[q] = sid[wl][jj + q];
                    wv[q] = sel4(swq[wl][jj + q], h);
                }
                float4 v[8];
#pragma unroll
                for (int q = 0; q < 8; q++)
                    v[q] = __ldg(((const float4*)g_xh) + (size_t)si[q] * 32 + lane);
#pragma unroll
                for (int q = 0; q < 8; q++) {
                    if (q & 1) {
                        accB.x += wv[q] * v[q].x; accB.y += wv[q] * v[q].y;
                        accB.z += wv[q] * v[q].z; accB.w += wv[q] * v[q].w;
                    } else {
                        acc.x += wv[q] * v[q].x; acc.y += wv[q] * v[q].y;
                        acc.z += wv[q] * v[q].z; acc.w += wv[q] * v[q].w;
                    }
                }
            }
            for (; jj + 2 <= deg; jj += 2) {
                int s0i = sid[wl][jj], s1i = sid[wl][jj + 1];
                float w0 = sel4(swq[wl][jj], h), w1 = sel4(swq[wl][jj + 1], h);
                float4 v0q = __ldg(((const float4*)g_xh) + (size_t)s0i * 32 + lane);
                float4 v1q = __ldg(((const float4*)g_xh) + (size_t)s1i * 32 + lane);
                acc.x += w0 * v0q.x; acc.y += w0 * v0q.y;
                acc.z += w0 * v0q.z; acc.w += w0 * v0q.w;
                accB.x += w1 * v1q.x; accB.y += w1 * v1q.y;
                accB.z += w1 * v1q.z; accB.w += w1 * v1q.w;
            }
            if (jj < deg) {
                int s0i = sid[wl][jj];
                float w0 = sel4(swq[wl][jj], h);
                float4 v0q = __ldg(((const float4*)g_xh) + (size_t)s0i * 32 + lane);
                acc.x += w0 * v0q.x; acc.y += w0 * v0q.y;
                acc.z += w0 * v0q.z; acc.w += w0 * v0q.w;
            }
            acc.x += accB.x; acc.y += accB.y; acc.z += accB.z; acc.w += accB.w;

            float4 g;
            g.x = acc.x * rdh + bq.x; g.y = acc.y * rdh + bq.y;
            g.z = acc.z * rdh + bq.z; g.w = acc.w * rdh + bq.w;
            ((float4*)g_acc)[(size_t)d * 32 + lane] = g;
            bs1[0] += g.x; bs1[1] += g.y; bs1[2] += g.z; bs1[3] += g.w;
            bs2[0] += g.x * g.x; bs2[1] += g.y * g.y;
            bs2[2] += g.z * g.z; bs2[3] += g.w * g.w;
        } else {
            // ---- fallback (deg > 64): weights staged in global g_w, with max ----
            float4 m = make_float4(NEG, NEG, NEG, NEG);
            for (int jj = lane; jj < deg; jj += 32) {
                int s = __ldg(g_csrc + start + jj);
                float4 as = __ldg(((const float4*)g_asrc) + s);
                float4 ae = __ldg(aeB + start + jj);
                aes.x += ae.x; aes.y += ae.y; aes.z += ae.z; aes.w += ae.w;
                float4 a;
                a.x = lrelu(as.x + ad.x + ae.x); a.y = lrelu(as.y + ad.y + ae.y);
                a.z = lrelu(as.z + ad.z + ae.z); a.w = lrelu(as.w + ad.w + ae.w);
                ((float4*)g_w)[start + jj] = a;
                m = fmax4(m, a);
            }
#pragma unroll
            for (int o = 16; o; o >>= 1) {
                m.x = fmaxf(m.x, __shfl_xor_sync(0xffffffffu, m.x, o));
                m.y = fmaxf(m.y, __shfl_xor_sync(0xffffffffu, m.y, o));
                m.z = fmaxf(m.z, __shfl_xor_sync(0xffffffffu, m.z, o));
                m.w = fmaxf(m.w, __shfl_xor_sync(0xffffffffu, m.w, o));
                aes.x += __shfl_xor_sync(0xffffffffu, aes.x, o);
                aes.y += __shfl_xor_sync(0xffffffffu, aes.y, o);
                aes.z += __shfl_xor_sync(0xffffffffu, aes.z, o);
                aes.w += __shfl_xor_sync(0xffffffffu, aes.w, o);
            }
            float rdeg = 1.f / (float)deg;
            float4 asf;
            asf.x = lrelu(asd.x + ad.x + aes.x * rdeg);
            asf.y = lrelu(asd.y + ad.y + aes.y * rdeg);
            asf.z = lrelu(asd.z + ad.z + aes.z * rdeg);
            asf.w = lrelu(asd.w + ad.w + aes.w * rdeg);
            m = fmax4(m, asf);

            for (int jj = lane; jj < deg; jj += 32) {
                float4 a = ((const float4*)g_w)[start + jj];
                a.x = __expf(a.x - m.x); a.y = __expf(a.y - m.y);
                a.z = __expf(a.z - m.z); a.w = __expf(a.w - m.w);
                ((float4*)g_w)[start + jj] = a;
                den.x += a.x; den.y += a.y; den.z += a.z; den.w += a.w;
            }
#pragma unroll
            for (int o = 16; o; o >>= 1) {
                den.x += __shfl_xor_sync(0xffffffffu, den.x, o);
                den.y += __shfl_xor_sync(0xffffffffu, den.y, o);
                den.z += __shfl_xor_sync(0xffffffffu, den.z, o);
                den.w += __shfl_xor_sync(0xffffffffu, den.w, o);
            }
            __syncwarp();
            float asfh = sel4(asf, h), mh = sel4(m, h), denh = sel4(den, h);
            float wsh = __expf(asfh - mh);
            float rdh = 1.f / (denh + wsh + 1e-16f);

            float4 acc = __ldg(((const float4*)g_xh) + (size_t)d * 32 + lane);
            acc.x *= wsh; acc.y *= wsh; acc.z *= wsh; acc.w *= wsh;
            for (int jj = 0; jj < deg; jj++) {
                float w = __ldg(g_w + (size_t)(start + jj) * 4 + h);
                int s = __ldg(g_csrc + start + jj);
                float4 v = __ldg(((const float4*)g_xh) + (size_t)s * 32 + lane);
                acc.x += w * v.x; acc.y += w * v.y;
                acc.z += w * v.z; acc.w += w * v.w;
            }
            float4 g;
            g.x = acc.x * rdh + bq.x; g.y = acc.y * rdh + bq.y;
            g.z = acc.z * rdh + bq.z; g.w = acc.w * rdh + bq.w;
            ((float4*)g_acc)[(size_t)d * 32 + lane] = g;
            bs1[0] += g.x; bs1[1] += g.y; bs1[2] += g.z; bs1[3] += g.w;
            bs2[0] += g.x * g.x; bs2[1] += g.y * g.y;
            bs2[2] += g.z * g.z; bs2[3] += g.w * g.w;
        }

        d = dn; start = nstart; deg = ndeg; ad = nad; asd = nasd;
    }

    // block-level BN reduction (8 warps x 128 channels)
#pragma unroll
    for (int q = 0; q < 4; q++) sred[wl][4 * lane + q] = bs1[q];
    __syncthreads();
    if (threadIdx.x < 128) {
        float s = 0.f;
#pragma unroll
        for (int w = 0; w < 8; w++) s += sred[w][threadIdx.x];
        atomicAdd(&g_bnsum[threadIdx.x], (double)s);
    }
    __syncthreads();
#pragma unroll
    for (int q = 0; q < 4; q++) sred[wl][4 * lane + q] = bs2[q];
    __syncthreads();
    if (threadIdx.x < 128) {
        float s = 0.f;
#pragma unroll
        for (int w = 0; w < 8; w++) s += sred[w][threadIdx.x];
        atomicAdd(&g_bnsq[threadIdx.x], (double)s);
    }

    // ---- fused bnstats: last block computes scale/shift, resets sums/counter ----
    __shared__ bool isLast;
    __threadfence();
    if (threadIdx.x == 0)
        isLast = (atomicAdd(&g_ctr, 1u) == gridDim.x - 1u);
    __syncthreads();
    if (isLast) {
        if (threadIdx.x < 128) {
            int c = threadIdx.x;
            double mu = g_bnsum[c] / (double)N;
            double var = g_bnsq[c] / (double)N - mu * mu;
            float rstd = (float)rsqrt(var + 1e-5);
            float ga = gamma[l * 128 + c];
            g_bnscale[c] = ga * rstd;
            g_bnshift[c] = beta[l * 128 + c] - ga * (float)mu * rstd;
            g_bnsum[c] = 0.0;
            g_bnsq[c] = 0.0;
        }
        if (threadIdx.x == 0) g_ctr = 0;
    }
}

// ---------------- launcher ----------------
extern "C" void kernel_launch(void* const* d_in, const int* in_sizes, int n_in,
                              void* d_out, int out_size) {
    (void)n_in; (void)out_size;
    const float* x         = (const float*)d_in[0];
    const int*   ei        = (const int*)  d_in[1];
    const float* edge_attr = (const float*)d_in[2];
    const float* W_atom    = (const float*)d_in[3];
    const float* b_atom    = (const float*)d_in[4];
    const float* W_bond    = (const float*)d_in[5];
    const float* b_bond    = (const float*)d_in[6];
    const float* W_lin     = (const float*)d_in[7];
    const float* W_edge    = (const float*)d_in[8];
    const float* att_src   = (const float*)d_in[9];
    const float* att_dst   = (const float*)d_in[10];
    const float* att_edge  = (const float*)d_in[11];
    const float* bias_conv = (const float*)d_in[12];
    const float* bn_gamma  = (const float*)d_in[13];
    const float* bn_beta   = (const float*)d_in[14];
    const float* W_out     = (const float*)d_in[15];
    const float* b_out     = (const float*)d_in[16];
    float* out = (float*)d_out;

    const int N = in_sizes[0] / 64;
    const int E = in_sizes[1] / 2;
    const int nb = (N + SCAN_BLK - 1) / SCAN_BLK;
    const int nz = (N + 255) / 256;

    const int smem128 = (128 * 128 + 64 * 132) * 4;
    const int smem64  = (64 * 128 + 64 * 68) * 4;
    cudaFuncSetAttribute(gemm_kernel<128, false, true,  true>,  cudaFuncAttributeMaxDynamicSharedMemorySize, smem128);
    cudaFuncSetAttribute(gemm_kernel<128, true,  true,  true>,  cudaFuncAttributeMaxDynamicSharedMemorySize, smem128);
    cudaFuncSetAttribute(gemm_kernel<128, true,  false, false>, cudaFuncAttributeMaxDynamicSharedMemorySize, smem128);
    cudaFuncSetAttribute(gemm_kernel<64,  false, false, true>,  cudaFuncAttributeMaxDynamicSharedMemorySize, smem64);

    float* ph;   cudaGetSymbolAddress((void**)&ph,   g_h);
    float* pxh;  cudaGetSymbolAddress((void**)&pxh,  g_xh);
    float* pacc; cudaGetSymbolAddress((void**)&pacc, g_acc);

    // ---- preprocessing: zeros+consts (fused), deg, scan, CSR scatter ----
    prep_kernel<<<nz + 12, 256>>>(nz, N, W_edge, att_edge, W_bond, b_bond);
    edge_prep_kernel<<<(E + 255) / 256, 256>>>(ei, E);
    scan_sum_kernel<<<nb, SCAN_BLK>>>(N);
    scan_final_kernel<<<nb, SCAN_BLK>>>(N, nb);
    scatter_kernel<<<(E + 255) / 256, 256>>>(ei, edge_attr, E);

    // ---- atom embedding ----
    gemm_kernel<64, false, false, true><<<(N + 63) / 64, 256, smem64>>>(
        x, W_atom, b_atom, ph, nullptr, nullptr, nullptr, 0, N);

    for (int l = 0; l < 3; l++) {
        if (l == 0)
            gemm_kernel<128, false, true, true><<<(N + 63) / 64, 256, smem128>>>(
                ph, W_lin, nullptr, pxh, nullptr, att_src, att_dst, 0, N);
        else
            gemm_kernel<128, true, true, true><<<(N + 63) / 64, 256, smem128>>>(
                pacc, W_lin + l * 128 * 128, nullptr, pxh, ph, att_src, att_dst, l, N);
        gat_kernel<<<1184, 256>>>(bias_conv, bn_gamma, bn_beta, l, N);
    }

    // output projection: fused BN+ReLU+residual of layer 3, no residual writeback
    gemm_kernel<128, true, false, false><<<(N + 63) / 64, 256, smem128>>>(
        pacc, W_out, b_out, out, ph, nullptr, nullptr, 0, N);
}

// round 17
// speedup vs baseline: 1.4839x; 1.4839x over previous
#include <cuda_runtime.h>
#include <math.h>

// ---------------- problem constants ----------------
#define HIDC 128
#define NMAX 50000
#define EMAX 600000
#define SCAN_BLK 512

// ---------------- device scratch ----------------
__device__ __align__(128) float g_h    [NMAX * HIDC];
__device__ __align__(128) float g_xh   [NMAX * HIDC];
__device__ __align__(128) float g_acc  [NMAX * HIDC];
__device__ __align__(128) float g_asrc [NMAX * 4];
__device__ __align__(128) float g_adst [NMAX * 4];
__device__ __align__(128) float g_M    [3 * 64];
__device__ __align__(128) float g_c    [3 * 4];
__device__ int   g_degi  [NMAX];
__device__ int   g_fill  [NMAX];
__device__ int   g_rowptr[NMAX];
__device__ int   g_bsum  [256];
__device__ __align__(128) int   g_csrc[EMAX];
__device__ __align__(128) float g_ae  [3][EMAX * 4];   // folded edge logits, CSR order
__device__ __align__(128) float g_w   [EMAX * 4];      // fallback scratch (deg>64 only)
__device__ double g_bnsum[HIDC];
__device__ double g_bnsq [HIDC];
__device__ __align__(128) float g_bnscale[HIDC];
__device__ __align__(128) float g_bnshift[HIDC];
__device__ unsigned int g_ctr = 0;

// ---------------- helpers ----------------
__device__ __forceinline__ float lrelu(float a) { return a > 0.f ? a : 0.2f * a; }

__device__ __forceinline__ unsigned long long pack2(float a) {
    unsigned long long r;
    asm("mov.b64 %0, {%1, %1};" : "=l"(r) : "r"(__float_as_uint(a)));
    return r;
}
__device__ __forceinline__ float2 unpack2(unsigned long long v) {
    unsigned int lo, hi;
    asm("mov.b64 {%0, %1}, %2;" : "=r"(lo), "=r"(hi) : "l"(v));
    return make_float2(__uint_as_float(lo), __uint_as_float(hi));
}
#define FMA2(acc, a2, b2) \
    asm("fma.rn.f32x2 %0, %1, %2, %0;" : "+l"(acc) : "l"(a2), "l"(b2))

__device__ __forceinline__ float sel4(float4 v, int h) {
    float ab = (h & 1) ? v.y : v.x;
    float cd = (h & 1) ? v.w : v.z;
    return (h & 2) ? cd : ab;
}
__device__ __forceinline__ float4 fmax4(float4 a, float4 b) {
    return make_float4(fmaxf(a.x, b.x), fmaxf(a.y, b.y), fmaxf(a.z, b.z), fmaxf(a.w, b.w));
}

// ---------------- prep: zeros ----------------
__global__ void prep_zero_kernel(int N) {
    int i = blockIdx.x * blockDim.x + threadIdx.x;
    if (i < N) { g_degi[i] = 0; g_fill[i] = 0; }
    if (i < 128) { g_bnsum[i] = 0.0; g_bnsq[i] = 0.0; }
}

// ---------------- per-layer folded constants (one block per (layer, head)) ----------------
__global__ void consts_kernel(const float* __restrict__ W_edge,
                              const float* __restrict__ att_edge,
                              const float* __restrict__ W_bond,
                              const float* __restrict__ b_bond) {
    __shared__ float Ve[128];
    const int t = threadIdx.x;          // 128 threads = j index
    const int l = blockIdx.x >> 2;      // layer
    const int h = blockIdx.x & 3;       // head
    const float* We = W_edge + l * 128 * 128 + t * 128 + h * 32;
    const float* ae = att_edge + l * 128 + h * 32;
    float v = 0.f;
#pragma unroll
    for (int d = 0; d < 32; d++) v += We[d] * ae[d];
    Ve[t] = v;
    __syncthreads();
    if (t < 16) {
        float m = 0.f;
        const float* wb = W_bond + t * 128;
#pragma unroll 4
        for (int k = 0; k < 128; k++) m += wb[k] * Ve[k];
        g_M[l * 64 + t * 4 + h] = m;
    } else if (t == 16) {
        float cc = 0.f;
        for (int k = 0; k < 128; k++) cc += b_bond[k] * Ve[k];
        g_c[l * 4 + h] = cc;
    }
}

// ---------------- degree histogram only ----------------
__global__ void edge_prep_kernel(const int* __restrict__ ei, int E) {
    int e = blockIdx.x * blockDim.x + threadIdx.x;
    if (e < E) atomicAdd(&g_degi[ei[E + e]], 1);
}

// ---------------- exclusive scan of degi -> rowptr ----------------
__global__ void scan_sum_kernel(int N) {
    __shared__ int sh[16];
    int b = blockIdx.x, t = threadIdx.x;
    int i = b * SCAN_BLK + t;
    int v = (i < N) ? g_degi[i] : 0;
#pragma unroll
    for (int o = 16; o; o >>= 1) v += __shfl_xor_sync(0xffffffffu, v, o);
    if ((t & 31) == 0) sh[t >> 5] = v;
    __syncthreads();
    if (t < 16) {
        int s = sh[t];
#pragma unroll
        for (int o = 8; o; o >>= 1) s += __shfl_xor_sync(0xffffu, s, o);
        if (t == 0) g_bsum[b] = s;
    }
}
__global__ void scan_mid_kernel(int nb) {
    __shared__ int ws[4];
    int t = threadIdx.x;   // 128 threads
    int lane = t & 31, w = t >> 5;
    int v = (t < nb) ? g_bsum[t] : 0;
    int x = v;
#pragma unroll
    for (int o = 1; o < 32; o <<= 1) {
        int y = __shfl_up_sync(0xffffffffu, x, o);
        if (lane >= o) x += y;
    }
    if (lane == 31) ws[w] = x;
    __syncthreads();
    if (t == 0) {
        int acc = 0;
#pragma unroll
        for (int q = 0; q < 4; q++) { int s = ws[q]; ws[q] = acc; acc += s; }
    }
    __syncthreads();
    if (t < nb) g_bsum[t] = x - v + ws[w];
}
__global__ void scan_final_kernel(int N) {
    __shared__ int wsum[16];
    int b = blockIdx.x, t = threadIdx.x;
    int i = b * SCAN_BLK + t;
    int v = (i < N) ? g_degi[i] : 0;
    int x = v;
#pragma unroll
    for (int o = 1; o < 32; o <<= 1) {
        int y = __shfl_up_sync(0xffffffffu, x, o);
        if ((t & 31) >= o) x += y;
    }
    if ((t & 31) == 31) wsum[t >> 5] = x;
    __syncthreads();
    if (t == 0) {
        int acc = 0;
        for (int w = 0; w < 16; w++) { int s = wsum[w]; wsum[w] = acc; acc += s; }
    }
    __syncthreads();
    if (i < N) g_rowptr[i] = x - v + wsum[t >> 5] + g_bsum[b];
}

// ---------------- counting-sort scatter: csr_src + folded edge logits per layer ----------------
__global__ void scatter_kernel(const int* __restrict__ ei,
                               const float* __restrict__ edge_attr, int E) {
    __shared__ float Ms[192];
    __shared__ float Cs[12];
    int t = threadIdx.x;
    if (t < 192) Ms[t] = g_M[t];
    if (t < 12)  Cs[t] = g_c[t];
    __syncthreads();
    int e = blockIdx.x * blockDim.x + t;
    if (e >= E) return;
    int s = ei[e], d = ei[E + e];
    int pos = g_rowptr[d] + atomicAdd(&g_fill[d], 1);
    g_csrc[pos] = s;
    float ev[16];
    const float4* ep = ((const float4*)edge_attr) + e * 4;
#pragma unroll
    for (int q = 0; q < 4; q++) {
        float4 v = ep[q];
        ev[4 * q] = v.x; ev[4 * q + 1] = v.y; ev[4 * q + 2] = v.z; ev[4 * q + 3] = v.w;
    }
#pragma unroll
    for (int l = 0; l < 3; l++) {
        float a0 = Cs[l * 4 + 0], a1 = Cs[l * 4 + 1], a2 = Cs[l * 4 + 2], a3 = Cs[l * 4 + 3];
#pragma unroll
        for (int k = 0; k < 16; k++) {
            float v = ev[k];
            a0 += v * Ms[l * 64 + k * 4 + 0]; a1 += v * Ms[l * 64 + k * 4 + 1];
            a2 += v * Ms[l * 64 + k * 4 + 2]; a3 += v * Ms[l * 64 + k * 4 + 3];
        }
        ((float4*)g_ae[l])[pos] = make_float4(a0, a1, a2, a3);
    }
}

// ---------------- GEMM: C[M,128] = A'[M,K] @ B[K,128] (+ bias) ----------------
// FUSEBN: A' = relu(A*bnscale+bnshift) + hres; WRITEH: write A' back to hres.
template <int K, bool FUSEBN, bool ATT, bool WRITEH>
__global__ __launch_bounds__(256) void gemm_kernel(const float* __restrict__ A,
                                                   const float* __restrict__ B,
                                                   const float* __restrict__ bias,
                                                   float* __restrict__ C,
                                                   float* __restrict__ hres,
                                                   const float* __restrict__ att_src,
                                                   const float* __restrict__ att_dst,
                                                   int l, int M) {
    constexpr int AST = K + 4;
    extern __shared__ float sm[];
    float* Bs = sm;               // K*128
    float* As = sm + K * 128;     // 64*AST
    const int t = threadIdx.x;
    const int row0 = blockIdx.x * 64;

    for (int idx = t; idx < K * 32; idx += 256)
        ((float4*)Bs)[idx] = ((const float4*)B)[idx];

    constexpr int KQ = K / 4;
    for (int idx = t; idx < 64 * KQ; idx += 256) {
        int r = idx / KQ, q = idx - r * KQ;
        int grow = row0 + r;
        float4 o = make_float4(0.f, 0.f, 0.f, 0.f);
        if (grow < M) {
            float4 v = ((const float4*)(A + (size_t)grow * K))[q];
            if (FUSEBN) {
                float4 hv = ((const float4*)(hres + (size_t)grow * K))[q];
                float4 sc = __ldg(((const float4*)g_bnscale) + q);
                float4 sh = __ldg(((const float4*)g_bnshift) + q);
                o.x = fmaxf(fmaf(v.x, sc.x, sh.x), 0.f) + hv.x;
                o.y = fmaxf(fmaf(v.y, sc.y, sh.y), 0.f) + hv.y;
                o.z = fmaxf(fmaf(v.z, sc.z, sh.z), 0.f) + hv.z;
                o.w = fmaxf(fmaf(v.w, sc.w, sh.w), 0.f) + hv.w;
                if (WRITEH) ((float4*)(hres + (size_t)grow * K))[q] = o;
            } else {
                o = v;
            }
        }
        *(float4*)(As + r * AST + 4 * q) = o;
    }
    __syncthreads();

    const int j = t & 15;   // cols 8j..8j+7
    const int i = t >> 4;   // rows 4i..4i+3
    unsigned long long acc2[4][4] = {};

    const float* aBase = As + (4 * i) * AST;
    const ulonglong2* BsP = (const ulonglong2*)Bs;
#pragma unroll 2
    for (int k4 = 0; k4 < K / 4; k4++) {
        float4 av[4];
#pragma unroll
        for (int r = 0; r < 4; r++)
            av[r] = *(const float4*)(aBase + r * AST + 4 * k4);
#pragma unroll
        for (int kk = 0; kk < 4; kk++) {
            int k = 4 * k4 + kk;
            ulonglong2 b01 = BsP[k * 32 + 2 * j];
            ulonglong2 b23 = BsP[k * 32 + 2 * j + 1];
#pragma unroll
            for (int r = 0; r < 4; r++) {
                unsigned long long ap = pack2(((const float*)&av[r])[kk]);
                FMA2(acc2[r][0], ap, b01.x);
                FMA2(acc2[r][1], ap, b01.y);
                FMA2(acc2[r][2], ap, b23.x);
                FMA2(acc2[r][3], ap, b23.y);
            }
        }
    }

    float4 bb0 = make_float4(0.f, 0.f, 0.f, 0.f), bb1 = bb0;
    if (bias) { bb0 = ((const float4*)bias)[2 * j]; bb1 = ((const float4*)bias)[2 * j + 1]; }

    float4 s0, s1, d0, d1;
    if (ATT) {
        s0 = __ldg(((const float4*)(att_src + l * 128)) + 2 * j);
        s1 = __ldg(((const float4*)(att_src + l * 128)) + 2 * j + 1);
        d0 = __ldg(((const float4*)(att_dst + l * 128)) + 2 * j);
        d1 = __ldg(((const float4*)(att_dst + l * 128)) + 2 * j + 1);
    }
    float ps[4], pd[4];

#pragma unroll
    for (int r = 0; r < 4; r++) {
        int grow = row0 + 4 * i + r;
        float2 p0 = unpack2(acc2[r][0]);
        float2 p1 = unpack2(acc2[r][1]);
        float2 p2 = unpack2(acc2[r][2]);
        float2 p3 = unpack2(acc2[r][3]);
        float4 o0 = make_float4(p0.x + bb0.x, p0.y + bb0.y, p1.x + bb0.z, p1.y + bb0.w);
        float4 o1 = make_float4(p2.x + bb1.x, p2.y + bb1.y, p3.x + bb1.z, p3.y + bb1.w);
        if (grow < M) {
            float4* cp = (float4*)(C + (size_t)grow * 128);
            cp[2 * j]     = o0;
            cp[2 * j + 1] = o1;
        }
        if (ATT) {
            ps[r] = o0.x * s0.x + o0.y * s0.y + o0.z * s0.z + o0.w * s0.w
                  + o1.x * s1.x + o1.y * s1.y + o1.z * s1.z + o1.w * s1.w;
            pd[r] = o0.x * d0.x + o0.y * d0.y + o0.z * d0.z + o0.w * d0.w
                  + o1.x * d1.x + o1.y * d1.y + o1.z * d1.z + o1.w * d1.w;
        }
    }

    if (ATT) {
#pragma unroll
        for (int r = 0; r < 4; r++) {
#pragma unroll
            for (int o = 1; o < 4; o <<= 1) {
                ps[r] += __shfl_xor_sync(0xffffffffu, ps[r], o);
                pd[r] += __shfl_xor_sync(0xffffffffu, pd[r], o);
            }
        }
        if ((j & 3) == 0) {
            const int hh = j >> 2;
#pragma unroll
            for (int r = 0; r < 4; r++) {
                int grow = row0 + 4 * i + r;
                if (grow >= M) continue;
                g_asrc[grow * 4 + hh] = ps[r];
                g_adst[grow * 4 + hh] = pd[r];
            }
        }
    }
}

// ---------------- fused GAT: softmax + aggregate + BN stats (fused bnstats tail) ----------------
__global__ __launch_bounds__(256) void gat_kernel(const float* __restrict__ bias_conv,
                                                  const float* __restrict__ gamma,
                                                  const float* __restrict__ beta,
                                                  int l, int N) {
    __shared__ float4 swq[8][64];    // per-warp exp'd weights
    __shared__ int    sid[8][64];    // per-warp neighbor indices
    __shared__ float  sred[8][128];

    const int lane = threadIdx.x & 31;
    const int wl = threadIdx.x >> 5;
    const int warpsTotal = (gridDim.x * blockDim.x) >> 5;
    const int h = lane >> 3;
    const float4* aeB = (const float4*)g_ae[l];
    const float4 bq = __ldg(((const float4*)(bias_conv + l * 128)) + lane);
    const float NEG = -3.0e38f;

    float bs1[4] = {0.f, 0.f, 0.f, 0.f};
    float bs2[4] = {0.f, 0.f, 0.f, 0.f};

    int d = (blockIdx.x * blockDim.x + threadIdx.x) >> 5;
    int start = 0, deg = 0;
    float4 ad, asd;
    if (d < N) {
        start = __ldg(g_rowptr + d);
        deg   = __ldg(g_degi + d);
        ad    = __ldg(((const float4*)g_adst) + d);
        asd   = __ldg(((const float4*)g_asrc) + d);
    }

    while (d < N) {
        const int dn = d + warpsTotal;
        int nstart = 0, ndeg = 0;
        float4 nad, nasd;
        if (dn < N) {
            nstart = __ldg(g_rowptr + dn);
            ndeg   = __ldg(g_degi + dn);
            nad    = __ldg(((const float4*)g_adst) + dn);
            nasd   = __ldg(((const float4*)g_asrc) + dn);
        }

        float4 aes = make_float4(0.f, 0.f, 0.f, 0.f);
        float4 den = make_float4(0.f, 0.f, 0.f, 0.f);

        if (deg <= 64) {
            const bool v0 = lane < deg, v1 = lane + 32 < deg;
            if (v0) {
                int s = __ldg(g_csrc + start + lane);
                sid[wl][lane] = s;
                float4 as = __ldg(((const float4*)g_asrc) + s);
                float4 ae = __ldg(aeB + start + lane);
                aes.x += ae.x; aes.y += ae.y; aes.z += ae.z; aes.w += ae.w;
                float4 e;
                e.x = __expf(lrelu(as.x + ad.x + ae.x));
                e.y = __expf(lrelu(as.y + ad.y + ae.y));
                e.z = __expf(lrelu(as.z + ad.z + ae.z));
                e.w = __expf(lrelu(as.w + ad.w + ae.w));
                swq[wl][lane] = e;
                den.x += e.x; den.y += e.y; den.z += e.z; den.w += e.w;
            }
            if (v1) {
                int s = __ldg(g_csrc + start + lane + 32);
                sid[wl][lane + 32] = s;
                float4 as = __ldg(((const float4*)g_asrc) + s);
                float4 ae = __ldg(aeB + start + lane + 32);
                aes.x += ae.x; aes.y += ae.y; aes.z += ae.z; aes.w += ae.w;
                float4 e;
                e.x = __expf(lrelu(as.x + ad.x + ae.x));
                e.y = __expf(lrelu(as.y + ad.y + ae.y));
                e.z = __expf(lrelu(as.z + ad.z + ae.z));
                e.w = __expf(lrelu(as.w + ad.w + ae.w));
                swq[wl][lane + 32] = e;
                den.x += e.x; den.y += e.y; den.z += e.z; den.w += e.w;
            }
#pragma unroll
            for (int o = 16; o; o >>= 1) {
                aes.x += __shfl_xor_sync(0xffffffffu, aes.x, o);
                aes.y += __shfl_xor_sync(0xffffffffu, aes.y, o);
                aes.z += __shfl_xor_sync(0xffffffffu, aes.z, o);
                aes.w += __shfl_xor_sync(0xffffffffu, aes.w, o);
                den.x += __shfl_xor_sync(0xffffffffu, den.x, o);
                den.y += __shfl_xor_sync(0xffffffffu, den.y, o);
                den.z += __shfl_xor_sync(0xffffffffu, den.z, o);
                den.w += __shfl_xor_sync(0xffffffffu, den.w, o);
            }
            float asfh;
            if (deg > 0) {
                float rdeg = 1.f / (float)deg;
                asfh = lrelu(sel4(asd, h) + sel4(ad, h) + sel4(aes, h) * rdeg);
            } else {
                asfh = lrelu(sel4(asd, h) + sel4(ad, h));
            }
            float wsh = __expf(asfh);
            float rdh = 1.f / (sel4(den, h) + wsh + 1e-16f);
            __syncwarp();

            float4 acc = __ldg(((const float4*)g_xh) + (size_t)d * 32 + lane);
            acc.x *= wsh; acc.y *= wsh; acc.z *= wsh; acc.w *= wsh;
            float4 accB = make_float4(0.f, 0.f, 0.f, 0.f);

            int jj = 0;
            for (; jj + 8 <= deg; jj += 8) {
                int   si[8];
                float wv[8];
#pragma unroll
                for (int q = 0; q < 8; q++) {
                    si[q] = sid[wl][jj + q];
                    wv[q] = sel4(swq[wl][jj + q], h);
                }
                float4 v[8];
#pragma unroll
                for (int q = 0; q < 8; q++)
                    v[q] = __ldg(((const float4*)g_xh) + (size_t)si[q] * 32 + lane);
#pragma unroll
                for (int q = 0; q < 8; q++) {
                    if (q & 1) {
                        accB.x += wv[q] * v[q].x; accB.y += wv[q] * v[q].y;
                        accB.z += wv[q] * v[q].z; accB.w += wv[q] * v[q].w;
                    } else {
                        acc.x += wv[q] * v[q].x; acc.y += wv[q] * v[q].y;
                        acc.z += wv[q] * v[q].z; acc.w += wv[q] * v[q].w;
                    }
                }
            }
            for (; jj + 2 <= deg; jj += 2) {
                int s0i = sid[wl][jj], s1i = sid[wl][jj + 1];
                float w0 = sel4(swq[wl][jj], h), w1 = sel4(swq[wl][jj + 1], h);
                float4 v0q = __ldg(((const float4*)g_xh) + (size_t)s0i * 32 + lane);
                float4 v1q = __ldg(((const float4*)g_xh) + (size_t)s1i * 32 + lane);
                acc.x += w0 * v0q.x; acc.y += w0 * v0q.y;
                acc.z += w0 * v0q.z; acc.w += w0 * v0q.w;
                accB.x += w1 * v1q.x; accB.y += w1 * v1q.y;
                accB.z += w1 * v1q.z; accB.w += w1 * v1q.w;
            }
            if (jj < deg) {
                int s0i = sid[wl][jj];
                float w0 = sel4(swq[wl][jj], h);
                float4 v0q = __ldg(((const float4*)g_xh) + (size_t)s0i * 32 + lane);
                acc.x += w0 * v0q.x; acc.y += w0 * v0q.y;
                acc.z += w0 * v0q.z; acc.w += w0 * v0q.w;
            }
            acc.x += accB.x; acc.y += accB.y; acc.z += accB.z; acc.w += accB.w;

            float4 g;
            g.x = acc.x * rdh + bq.x; g.y = acc.y * rdh + bq.y;
            g.z = acc.z * rdh + bq.z; g.w = acc.w * rdh + bq.w;
            ((float4*)g_acc)[(size_t)d * 32 + lane] = g;
            bs1[0] += g.x; bs1[1] += g.y; bs1[2] += g.z; bs1[3] += g.w;
            bs2[0] += g.x * g.x; bs2[1] += g.y * g.y;
            bs2[2] += g.z * g.z; bs2[3] += g.w * g.w;
        } else {
            // ---- fallback (deg > 64): weights staged in global g_w, with max ----
            float4 m = make_float4(NEG, NEG, NEG, NEG);
            for (int jj = lane; jj < deg; jj += 32) {
                int s = __ldg(g_csrc + start + jj);
                float4 as = __ldg(((const float4*)g_asrc) + s);
                float4 ae = __ldg(aeB + start + jj);
                aes.x += ae.x; aes.y += ae.y; aes.z += ae.z; aes.w += ae.w;
                float4 a;
                a.x = lrelu(as.x + ad.x + ae.x); a.y = lrelu(as.y + ad.y + ae.y);
                a.z = lrelu(as.z + ad.z + ae.z); a.w = lrelu(as.w + ad.w + ae.w);
                ((float4*)g_w)[start + jj] = a;
                m = fmax4(m, a);
            }
#pragma unroll
            for (int o = 16; o; o >>= 1) {
                m.x = fmaxf(m.x, __shfl_xor_sync(0xffffffffu, m.x, o));
                m.y = fmaxf(m.y, __shfl_xor_sync(0xffffffffu, m.y, o));
                m.z = fmaxf(m.z, __shfl_xor_sync(0xffffffffu, m.z, o));
                m.w = fmaxf(m.w, __shfl_xor_sync(0xffffffffu, m.w, o));
                aes.x += __shfl_xor_sync(0xffffffffu, aes.x, o);
                aes.y += __shfl_xor_sync(0xffffffffu, aes.y, o);
                aes.z += __shfl_xor_sync(0xffffffffu, aes.z, o);
                aes.w += __shfl_xor_sync(0xffffffffu, aes.w, o);
            }
            float rdeg = 1.f / (float)deg;
            float4 asf;
            asf.x = lrelu(asd.x + ad.x + aes.x * rdeg);
            asf.y = lrelu(asd.y + ad.y + aes.y * rdeg);
            asf.z = lrelu(asd.z + ad.z + aes.z * rdeg);
            asf.w = lrelu(asd.w + ad.w + aes.w * rdeg);
            m = fmax4(m, asf);

            for (int jj = lane; jj < deg; jj += 32) {
                float4 a = ((const float4*)g_w)[start + jj];
                a.x = __expf(a.x - m.x); a.y = __expf(a.y - m.y);
                a.z = __expf(a.z - m.z); a.w = __expf(a.w - m.w);
                ((float4*)g_w)[start + jj] = a;
                den.x += a.x; den.y += a.y; den.z += a.z; den.w += a.w;
            }
#pragma unroll
            for (int o = 16; o; o >>= 1) {
                den.x += __shfl_xor_sync(0xffffffffu, den.x, o);
                den.y += __shfl_xor_sync(0xffffffffu, den.y, o);
                den.z += __shfl_xor_sync(0xffffffffu, den.z, o);
                den.w += __shfl_xor_sync(0xffffffffu, den.w, o);
            }
            __syncwarp();
            float asfh = sel4(asf, h), mh = sel4(m, h), denh = sel4(den, h);
            float wsh = __expf(asfh - mh);
            float rdh = 1.f / (denh + wsh + 1e-16f);

            float4 acc = __ldg(((const float4*)g_xh) + (size_t)d * 32 + lane);
            acc.x *= wsh; acc.y *= wsh; acc.z *= wsh; acc.w *= wsh;
            for (int jj = 0; jj < deg; jj++) {
                float w = __ldg(g_w + (size_t)(start + jj) * 4 + h);
                int s = __ldg(g_csrc + start + jj);
                float4 v = __ldg(((const float4*)g_xh) + (size_t)s * 32 + lane);
                acc.x += w * v.x; acc.y += w * v.y;
                acc.z += w * v.z; acc.w += w * v.w;
            }
            float4 g;
            g.x = acc.x * rdh + bq.x; g.y = acc.y * rdh + bq.y;
            g.z = acc.z * rdh + bq.z; g.w = acc.w * rdh + bq.w;
            ((float4*)g_acc)[(size_t)d * 32 + lane] = g;
            bs1[0] += g.x; bs1[1] += g.y; bs1[2] += g.z; bs1[3] += g.w;
            bs2[0] += g.x * g.x; bs2[1] += g.y * g.y;
            bs2[2] += g.z * g.z; bs2[3] += g.w * g.w;
        }

        d = dn; start = nstart; deg = ndeg; ad = nad; asd = nasd;
    }

    // block-level BN reduction (8 warps x 128 channels)
#pragma unroll
    for (int q = 0; q < 4; q++) sred[wl][4 * lane + q] = bs1[q];
    __syncthreads();
    if (threadIdx.x < 128) {
        float s = 0.f;
#pragma unroll
        for (int w = 0; w < 8; w++) s += sred[w][threadIdx.x];
        atomicAdd(&g_bnsum[threadIdx.x], (double)s);
    }
    __syncthreads();
#pragma unroll
    for (int q = 0; q < 4; q++) sred[wl][4 * lane + q] = bs2[q];
    __syncthreads();
    if (threadIdx.x < 128) {
        float s = 0.f;
#pragma unroll
        for (int w = 0; w < 8; w++) s += sred[w][threadIdx.x];
        atomicAdd(&g_bnsq[threadIdx.x], (double)s);
    }

    // ---- fused bnstats: last block computes scale/shift, resets sums/counter ----
    __shared__ bool isLast;
    __threadfence();
    if (threadIdx.x == 0)
        isLast = (atomicAdd(&g_ctr, 1u) == gridDim.x - 1u);
    __syncthreads();
    if (isLast) {
        if (threadIdx.x < 128) {
            int c = threadIdx.x;
            double mu = g_bnsum[c] / (double)N;
            double var = g_bnsq[c] / (double)N - mu * mu;
            float rstd = (float)rsqrt(var + 1e-5);
            float ga = gamma[l * 128 + c];
            g_bnscale[c] = ga * rstd;
            g_bnshift[c] = beta[l * 128 + c] - ga * (float)mu * rstd;
            g_bnsum[c] = 0.0;
            g_bnsq[c] = 0.0;
        }
        if (threadIdx.x == 0) g_ctr = 0;
    }
}

// ---------------- launcher ----------------
extern "C" void kernel_launch(void* const* d_in, const int* in_sizes, int n_in,
                              void* d_out, int out_size) {
    (void)n_in; (void)out_size;
    const float* x         = (const float*)d_in[0];
    const int*   ei        = (const int*)  d_in[1];
    const float* edge_attr = (const float*)d_in[2];
    const float* W_atom    = (const float*)d_in[3];
    const float* b_atom    = (const float*)d_in[4];
    const float* W_bond    = (const float*)d_in[5];
    const float* b_bond    = (const float*)d_in[6];
    const float* W_lin     = (const float*)d_in[7];
    const float* W_edge    = (const float*)d_in[8];
    const float* att_src   = (const float*)d_in[9];
    const float* att_dst   = (const float*)d_in[10];
    const float* att_edge  = (const float*)d_in[11];
    const float* bias_conv = (const float*)d_in[12];
    const float* bn_gamma  = (const float*)d_in[13];
    const float* bn_beta   = (const float*)d_in[14];
    const float* W_out     = (const float*)d_in[15];
    const float* b_out     = (const float*)d_in[16];
    float* out = (float*)d_out;

    const int N = in_sizes[0] / 64;
    const int E = in_sizes[1] / 2;
    const int nb = (N + SCAN_BLK - 1) / SCAN_BLK;

    const int smem128 = (128 * 128 + 64 * 132) * 4;
    const int smem64  = (64 * 128 + 64 * 68) * 4;
    cudaFuncSetAttribute(gemm_kernel<128, false, true,  true>,  cudaFuncAttributeMaxDynamicSharedMemorySize, smem128);
    cudaFuncSetAttribute(gemm_kernel<128, true,  true,  true>,  cudaFuncAttributeMaxDynamicSharedMemorySize, smem128);
    cudaFuncSetAttribute(gemm_kernel<128, true,  false, false>, cudaFuncAttributeMaxDynamicSharedMemorySize, smem128);
    cudaFuncSetAttribute(gemm_kernel<64,  false, false, true>,  cudaFuncAttributeMaxDynamicSharedMemorySize, smem64);

    float* ph;   cudaGetSymbolAddress((void**)&ph,   g_h);
    float* pxh;  cudaGetSymbolAddress((void**)&pxh,  g_xh);
    float* pacc; cudaGetSymbolAddress((void**)&pacc, g_acc);

    // ---- preprocessing: deg, folded consts, CSR counting sort ----
    prep_zero_kernel<<<(N + 255) / 256, 256>>>(N);
    consts_kernel<<<12, 128>>>(W_edge, att_edge, W_bond, b_bond);
    edge_prep_kernel<<<(E + 255) / 256, 256>>>(ei, E);
    scan_sum_kernel<<<nb, SCAN_BLK>>>(N);
    scan_mid_kernel<<<1, 128>>>(nb);
    scan_final_kernel<<<nb, SCAN_BLK>>>(N);
    scatter_kernel<<<(E + 255) / 256, 256>>>(ei, edge_attr, E);

    // ---- atom embedding ----
    gemm_kernel<64, false, false, true><<<(N + 63) / 64, 256, smem64>>>(
        x, W_atom, b_atom, ph, nullptr, nullptr, nullptr, 0, N);

    for (int l = 0; l < 3; l++) {
        if (l == 0)
            gemm_kernel<128, false, true, true><<<(N + 63) / 64, 256, smem128>>>(
                ph, W_lin, nullptr, pxh, nullptr, att_src, att_dst, 0, N);
        else
            gemm_kernel<128, true, true, true><<<(N + 63) / 64, 256, smem128>>>(
                pacc, W_lin + l * 128 * 128, nullptr, pxh, ph, att_src, att_dst, l, N);
        gat_kernel<<<1184, 256>>>(bias_conv, bn_gamma, bn_beta, l, N);
    }

    // output projection: fused BN+ReLU+residual of layer 3, no residual writeback
    gemm_kernel<128, true, false, false><<<(N + 63) / 64, 256, smem128>>>(
        pacc, W_out, b_out, out, ph, nullptr, nullptr, 0, N);
}